// round 14
// baseline (speedup 1.0000x reference)
#include <cuda_runtime.h>

#define NN    1024
#define OUTN  513
#define NIMG  48
#define TR    8            /* output rows per tile  */
#define TC    127          /* output cols per tile  */
#define ICOLS 256          /* = 2*TC + 2 : input cols per full tile */

__device__ __forceinline__ int symc(int i) {
    i = (i < 0)   ? (-1 - i)       : i;
    i = (i >= NN) ? (2*NN - 1 - i) : i;
    return i;
}

// filters reversed (true convolution): fr[k] = DEC[3-k]
#define FL0 ( 0.48296291314469025f)
#define FL1 ( 0.836516303737469f)
#define FL2 ( 0.22414386804185735f)
#define FL3 (-0.12940952255092145f)
#define FH0 (-0.12940952255092145f)
#define FH1 (-0.22414386804185735f)
#define FH2 ( 0.836516303737469f)
#define FH3 (-0.48296291314469025f)

__global__ __launch_bounds__(256, 6)
void dwt2_kernel(const float* __restrict__ x, float* __restrict__ out) {
    // interleaved (lo, hi) per vertical-transform element
    __shared__ __align__(16) float2 s[TR][ICOLS];

    const int z  = blockIdx.z;
    const int r0 = blockIdx.y * TR;
    const int c0 = blockIdx.x * TC;
    const float* __restrict__ img = x + (size_t)z * NN * NN;
    const int tid = threadIdx.x;

    const int ncols = min(TC, OUTN - c0);
    const int icols = 2 * ncols + 2;          // input cols actually needed
    const int rb0   = 2 * r0 - 2;             // first input row of tile
    const bool rowfast = (rb0 >= 0) && (rb0 + 2*TR + 1 < NN);

    // ---- Phase 1: vertical DWT, column-stationary, rolling row reuse ----
    for (int j = tid; j < icols; j += 256) {
        const int xi = symc(2*c0 - 2 + j);    // column index computed once
        if (rowfast) {
            const float* p = img + (size_t)rb0 * NN + xi;
            float a = p[0];
            float b = p[NN];
            p += 2 * NN;
            #pragma unroll
            for (int lr = 0; lr < TR; ++lr) {
                float c = p[0];
                float d = p[NN];
                s[lr][j] = make_float2(FL0*a + FL1*b + FL2*c + FL3*d,
                                       FH0*a + FH1*b + FH2*c + FH3*d);
                a = c; b = d;
                p += 2 * NN;
            }
        } else {
            float a = img[(size_t)symc(rb0)     * NN + xi];
            float b = img[(size_t)symc(rb0 + 1) * NN + xi];
            #pragma unroll
            for (int lr = 0; lr < TR; ++lr) {
                float c = img[(size_t)symc(rb0 + 2*lr + 2) * NN + xi];
                float d = img[(size_t)symc(rb0 + 2*lr + 3) * NN + xi];
                s[lr][j] = make_float2(FL0*a + FL1*b + FL2*c + FL3*d,
                                       FH0*a + FH1*b + FH2*c + FH3*d);
                a = c; b = d;
            }
        }
    }
    __syncthreads();

    // ---- Phase 2: horizontal DWT (lo filter on both lanes) ----
    float* __restrict__ cA = out;
    float* __restrict__ cH = out + (size_t)NIMG * OUTN * OUTN;

    const int lc  = tid & 127;        // column within tile (0..127; 127 idle)
    const int lr0 = tid >> 7;         // 0 or 1
    const int c   = c0 + lc;

    if (lc < TC && c < OUTN) {
        const int jb = 2 * lc;
        #pragma unroll
        for (int i = 0; i < TR / 2; ++i) {
            const int lr = lr0 + 2 * i;
            const int r  = r0 + lr;
            if (r < OUTN) {
                float4 q0 = *(const float4*)&s[lr][jb];      // lo0,hi0,lo1,hi1
                float4 q1 = *(const float4*)&s[lr][jb + 2];  // lo2,hi2,lo3,hi3
                float a = FL0*q0.x + FL1*q0.z + FL2*q1.x + FL3*q1.z;
                float h = FL0*q0.y + FL1*q0.w + FL2*q1.y + FL3*q1.w;
                size_t base = ((size_t)z * OUTN + r) * OUTN + c;
                cA[base] = a;
                cH[base] = h;
            }
        }
    }
}

extern "C" void kernel_launch(void* const* d_in, const int* in_sizes, int n_in,
                              void* d_out, int out_size) {
    const float* x = (const float*)d_in[0];
    float* out = (float*)d_out;
    dim3 grid((OUTN + TC - 1) / TC,    // 5
              (OUTN + TR - 1) / TR,    // 65
              NIMG);                   // 48
    dwt2_kernel<<<grid, 256>>>(x, out);
}

// round 15
// speedup vs baseline: 1.0310x; 1.0310x over previous
#include <cuda_runtime.h>

#define NN    1024
#define OUTN  513
#define NIMG  48
#define TR    8            /* output rows per tile  */
#define TC    127          /* output cols per tile  */
#define ICOLS 256          /* = 2*TC + 2 : input cols per full tile */

__device__ __forceinline__ int symc(int i) {
    i = (i < 0)   ? (-1 - i)       : i;
    i = (i >= NN) ? (2*NN - 1 - i) : i;
    return i;
}

// filters reversed (true convolution): fr[k] = DEC[3-k]
#define FL0 ( 0.48296291314469025f)
#define FL1 ( 0.836516303737469f)
#define FL2 ( 0.22414386804185735f)
#define FL3 (-0.12940952255092145f)
#define FH0 (-0.12940952255092145f)
#define FH1 (-0.22414386804185735f)
#define FH2 ( 0.836516303737469f)
#define FH3 (-0.48296291314469025f)

__global__ __launch_bounds__(256, 6)
void dwt2_kernel(const float* __restrict__ x, float* __restrict__ out) {
    // interleaved (lo, hi) per vertical-transform element
    __shared__ __align__(16) float2 s[TR][ICOLS];

    const int z  = blockIdx.z;
    const int r0 = blockIdx.y * TR;
    const int c0 = blockIdx.x * TC;
    const float* __restrict__ img = x + (size_t)z * NN * NN;
    const int tid = threadIdx.x;

    const int ncols = min(TC, OUTN - c0);
    const int icols = 2 * ncols + 2;          // input cols actually needed
    const int rb0   = 2 * r0 - 2;             // first input row of tile
    const bool rowfast = (rb0 >= 0) && (rb0 + 2*TR + 1 < NN);

    // ---- Phase 1: vertical DWT, column-stationary, rolling row reuse ----
    for (int j = tid; j < icols; j += 256) {
        const int xi = symc(2*c0 - 2 + j);    // column index computed once
        if (rowfast) {
            const float* p = img + (size_t)rb0 * NN + xi;
            float a = p[0];
            float b = p[NN];
            p += 2 * NN;
            #pragma unroll
            for (int lr = 0; lr < TR; ++lr) {
                float c = p[0];
                float d = p[NN];
                s[lr][j] = make_float2(FL0*a + FL1*b + FL2*c + FL3*d,
                                       FH0*a + FH1*b + FH2*c + FH3*d);
                a = c; b = d;
                p += 2 * NN;
            }
        } else {
            float a = img[(size_t)symc(rb0)     * NN + xi];
            float b = img[(size_t)symc(rb0 + 1) * NN + xi];
            #pragma unroll
            for (int lr = 0; lr < TR; ++lr) {
                float c = img[(size_t)symc(rb0 + 2*lr + 2) * NN + xi];
                float d = img[(size_t)symc(rb0 + 2*lr + 3) * NN + xi];
                s[lr][j] = make_float2(FL0*a + FL1*b + FL2*c + FL3*d,
                                       FH0*a + FH1*b + FH2*c + FH3*d);
                a = c; b = d;
            }
        }
    }
    __syncthreads();

    // ---- Phase 2: horizontal DWT (lo filter on both lanes) ----
    float* __restrict__ cA = out;
    float* __restrict__ cH = out + (size_t)NIMG * OUTN * OUTN;

    const int lc  = tid & 127;        // column within tile (0..127; 127 idle)
    const int lr0 = tid >> 7;         // 0 or 1
    const int c   = c0 + lc;

    if (lc < TC && c < OUTN) {
        const int jb = 2 * lc;
        #pragma unroll
        for (int i = 0; i < TR / 2; ++i) {
            const int lr = lr0 + 2 * i;
            const int r  = r0 + lr;
            if (r < OUTN) {
                float4 q0 = *(const float4*)&s[lr][jb];      // lo0,hi0,lo1,hi1
                float4 q1 = *(const float4*)&s[lr][jb + 2];  // lo2,hi2,lo3,hi3
                float a = FL0*q0.x + FL1*q0.z + FL2*q1.x + FL3*q1.z;
                float h = FL0*q0.y + FL1*q0.w + FL2*q1.y + FL3*q1.w;
                size_t base = ((size_t)z * OUTN + r) * OUTN + c;
                cA[base] = a;
                cH[base] = h;
            }
        }
    }
}

extern "C" void kernel_launch(void* const* d_in, const int* in_sizes, int n_in,
                              void* d_out, int out_size) {
    const float* x = (const float*)d_in[0];
    float* out = (float*)d_out;
    dim3 grid((OUTN + TC - 1) / TC,    // 5
              (OUTN + TR - 1) / TR,    // 65
              NIMG);                   // 48
    dwt2_kernel<<<grid, 256>>>(x, out);
}